// round 1
// baseline (speedup 1.0000x reference)
#include <cuda_runtime.h>
#include <cuda_bf16.h>
#include <cstdint>

#define DIM  512
#define KC   1024
#define TM   64
#define TN   64
#define TKD  16

// Scratch for centroid squared norms (no device allocations allowed).
__device__ float g_csq[KC];

// ||c_k||^2 for each centroid column k. centroids layout [D, K] row-major.
__global__ void csq_kernel(const float* __restrict__ c) {
    int k = blockIdx.x * blockDim.x + threadIdx.x;
    if (k < KC) {
        float s = 0.f;
        #pragma unroll 8
        for (int d = 0; d < DIM; d++) {
            float v = c[(size_t)d * KC + k];
            s += v * v;
        }
        g_csq[k] = s;
    }
}

// Fused GEMM + argmin.
// Block: 256 threads = 16x16 thread grid, each thread owns a 4x4 micro-tile
// of a 64(row) x 64(col) distance tile. Loop over all K in 64-col chunks,
// keeping per-row running (best, idx) in shared memory.
// distance surrogate: s(n,k) = ||c_k||^2 - 2 * <x_n, c_k>   (||x_n||^2 dropped)
__global__ __launch_bounds__(256) void assign_kernel(
    const float* __restrict__ A,   // features [N, D]
    const float* __restrict__ B,   // centroids [D, K]
    float* __restrict__ out,       // [N]
    int N)
{
    __shared__ float As[TKD][TM];        // A tile, transposed: [d][row]
    __shared__ float Bs[TKD][TN];        // B tile: [d][col]
    __shared__ float cand_val[TM][17];   // +1 pad vs bank conflicts
    __shared__ int   cand_idx[TM][17];
    __shared__ float best_val[TM];
    __shared__ int   best_idx[TM];

    const int tid = threadIdx.x;         // 0..255
    const int tx  = tid & 15;            // column-thread 0..15
    const int ty  = tid >> 4;            // row-thread 0..15
    const int row0 = blockIdx.x * TM;

    if (tid < TM) { best_val[tid] = 3.4e38f; best_idx[tid] = 0; }

    for (int kc = 0; kc < KC; kc += TN) {
        float acc[4][4];
        #pragma unroll
        for (int i = 0; i < 4; i++)
            #pragma unroll
            for (int j = 0; j < 4; j++) acc[i][j] = 0.f;

        for (int dc = 0; dc < DIM; dc += TKD) {
            // Load A tile: 64 rows x 16 d = 1024 floats = 256 float4, one per thread.
            {
                int r  = tid >> 2;          // row 0..63
                int d4 = (tid & 3) * 4;     // d offset 0,4,8,12
                float4 v = *reinterpret_cast<const float4*>(
                    &A[(size_t)(row0 + r) * DIM + dc + d4]);
                As[d4 + 0][r] = v.x;
                As[d4 + 1][r] = v.y;
                As[d4 + 2][r] = v.z;
                As[d4 + 3][r] = v.w;
            }
            // Load B tile: 16 d x 64 cols = 1024 floats = 256 float4.
            {
                int d  = tid >> 4;          // 0..15
                int c4 = (tid & 15) * 4;    // 0..60
                float4 v = *reinterpret_cast<const float4*>(
                    &B[(size_t)(dc + d) * KC + kc + c4]);
                *reinterpret_cast<float4*>(&Bs[d][c4]) = v;
            }
            __syncthreads();

            #pragma unroll
            for (int d = 0; d < TKD; d++) {
                float a[4], b[4];
                #pragma unroll
                for (int i = 0; i < 4; i++) a[i] = As[d][ty * 4 + i];
                #pragma unroll
                for (int j = 0; j < 4; j++) b[j] = Bs[d][tx * 4 + j];
                #pragma unroll
                for (int i = 0; i < 4; i++)
                    #pragma unroll
                    for (int j = 0; j < 4; j++) acc[i][j] += a[i] * b[j];
            }
            __syncthreads();
        }

        // Per-thread argmin over its 4 columns (ascending j -> first-index ties).
        #pragma unroll
        for (int i = 0; i < 4; i++) {
            float bv = 3.4e38f;
            int   bi = 0;
            #pragma unroll
            for (int j = 0; j < 4; j++) {
                int col = kc + tx * 4 + j;
                float dist = g_csq[col] - 2.0f * acc[i][j];
                if (dist < bv) { bv = dist; bi = col; }
            }
            cand_val[ty * 4 + i][tx] = bv;
            cand_idx[ty * 4 + i][tx] = bi;
        }
        __syncthreads();

        // One thread per row reduces the 16 column-thread candidates
        // (ascending tx -> ascending column -> first-index tie-breaking preserved).
        if (tid < TM) {
            float bv = best_val[tid];
            int   bi = best_idx[tid];
            #pragma unroll
            for (int t = 0; t < 16; t++) {
                float v = cand_val[tid][t];
                if (v < bv) { bv = v; bi = cand_idx[tid][t]; }
            }
            best_val[tid] = bv;
            best_idx[tid] = bi;
        }
        __syncthreads();
    }

    if (tid < TM) {
        int r = row0 + tid;
        if (r < N) out[r] = (float)best_idx[tid];
    }
}

extern "C" void kernel_launch(void* const* d_in, const int* in_sizes, int n_in,
                              void* d_out, int out_size) {
    const float* features  = (const float*)d_in[0];   // [N, 512]
    const float* centroids = (const float*)d_in[1];   // [512, 1024]
    float* out = (float*)d_out;                       // [N, 1] fp32 indices

    int N = in_sizes[0] / DIM;

    csq_kernel<<<(KC + 255) / 256, 256>>>(centroids);
    assign_kernel<<<(N + TM - 1) / TM, 256>>>(features, centroids, out, N);
}

// round 4
// speedup vs baseline: 2.6913x; 2.6913x over previous
#include <cuda_runtime.h>
#include <cuda_fp16.h>
#include <cstdint>

#define NROWS  131072
#define DIMD   512
#define KCOLS  1024
#define MT     128        // rows per CTA
#define NT     128        // cols per tile
#define KB     64         // d per chunk
#define NTILES (KCOLS/NT) // 8
#define DCH    (DIMD/KB)  // 8
#define THREADS 512
#define LOSCALE 1024.0f
#define INV_LOSCALE 9.765625e-4f

// smem layout
#define SM_CSQ   0                   // 128 floats
#define SM_TILES 1024
#define ARR_B    (128*128)           // 16384 bytes per [128][64] half array
#define STAGE_B  (4*ARR_B)           // Ahi, Alo, Bhi, Blo = 64KB
#define SMEM_TOTAL (SM_TILES + 2*STAGE_B)   // 132096

// ------------- device globals (no allocations allowed) -------------
__device__ __align__(128) __half g_Ahi[(size_t)NROWS*DIMD];
__device__ __align__(128) __half g_Alo[(size_t)NROWS*DIMD];
__device__ __align__(128) __half g_Bhi[(size_t)KCOLS*DIMD];   // transposed [k][d]
__device__ __align__(128) __half g_Blo[(size_t)KCOLS*DIMD];
__device__ __align__(128) float  g_Bt[(size_t)KCOLS*DIMD];    // fp32 transposed [k][d]
__device__ float g_csq[KCOLS];
__device__ int2  g_cand[NROWS];

// ------------- helpers -------------
__device__ __forceinline__ uint32_t smem_u32(const void* p) {
    uint32_t a;
    asm("{ .reg .u64 t; cvta.to.shared.u64 t, %1; cvt.u32.u64 %0, t; }" : "=r"(a) : "l"(p));
    return a;
}
__device__ __forceinline__ uint32_t sw128(uint32_t o) { return o ^ ((o >> 3) & 0x70); }

__device__ __forceinline__ void cp16(uint32_t s, const void* g) {
    size_t ga = __cvta_generic_to_global(g);
    asm volatile("cp.async.cg.shared.global [%0], [%1], 16;" :: "r"(s), "l"(ga) : "memory");
}

#define LDM_X4(r0,r1,r2,r3,addr) \
    asm volatile("ldmatrix.sync.aligned.m8n8.x4.shared.b16 {%0,%1,%2,%3}, [%4];" \
        : "=r"(r0),"=r"(r1),"=r"(r2),"=r"(r3) : "r"(addr))

#define MMA16816(d, a, b0, b1) \
    asm volatile("mma.sync.aligned.m16n8k16.row.col.f32.f16.f16.f32 " \
        "{%0,%1,%2,%3},{%4,%5,%6,%7},{%8,%9},{%0,%1,%2,%3};" \
        : "+f"((d)[0]),"+f"((d)[1]),"+f"((d)[2]),"+f"((d)[3]) \
        : "r"((a)[0]),"r"((a)[1]),"r"((a)[2]),"r"((a)[3]),"r"(b0),"r"(b1))

// ------------- precompute kernels -------------
__global__ void split_feat(const float* __restrict__ A) {
    size_t i = (size_t)blockIdx.x * blockDim.x + threadIdx.x;   // 8 elems each
    if (i >= (size_t)NROWS * DIMD / 8) return;
    const float4* a4 = reinterpret_cast<const float4*>(A) + i * 2;
    float4 v0 = a4[0], v1 = a4[1];
    float x[8] = {v0.x, v0.y, v0.z, v0.w, v1.x, v1.y, v1.z, v1.w};
    __half h[8], l[8];
    #pragma unroll
    for (int j = 0; j < 8; j++) {
        h[j] = __float2half_rn(x[j]);
        l[j] = __float2half_rn((x[j] - __half2float(h[j])) * LOSCALE);
    }
    reinterpret_cast<uint4*>(g_Ahi)[i] = *reinterpret_cast<uint4*>(h);
    reinterpret_cast<uint4*>(g_Alo)[i] = *reinterpret_cast<uint4*>(l);
}

__global__ void split_cent(const float* __restrict__ B) {
    int i = blockIdx.x * blockDim.x + threadIdx.x;   // over [k][d]
    if (i >= KCOLS * DIMD) return;
    int k = i / DIMD, d = i % DIMD;
    float x = B[(size_t)d * KCOLS + k];
    __half h = __float2half_rn(x);
    g_Bhi[i] = h;
    g_Blo[i] = __float2half_rn((x - __half2float(h)) * LOSCALE);
    g_Bt[i]  = x;
}

__global__ void csq_kernel(const float* __restrict__ c) {
    int k = blockIdx.x * blockDim.x + threadIdx.x;
    if (k < KCOLS) {
        float s = 0.f;
        #pragma unroll 8
        for (int d = 0; d < DIMD; d++) {
            float v = c[(size_t)d * KCOLS + k];
            s += v * v;
        }
        g_csq[k] = s;
    }
}

// ------------- phase 1: fused screening GEMM + top-2 -------------
__global__ __launch_bounds__(THREADS, 1) void assign_mma() {
    extern __shared__ char smem[];
    const uint32_t sb = smem_u32(smem);
    const int tid = threadIdx.x;
    const int lane = tid & 31;
    const int w = tid >> 5;
    const int mw = w >> 2;          // 0..3 (M)
    const int nw = w & 3;           // 0..3 (N)
    const int row0 = blockIdx.x * MT;
    float* csq_s = reinterpret_cast<float*>(smem + SM_CSQ);

    // ldmatrix address precomputes
    uint32_t aBase[2], aM[2], bBase[2], bM[2];
    #pragma unroll
    for (int mi = 0; mi < 2; mi++) {
        int r = mw * 32 + mi * 16 + (lane & 15);
        aBase[mi] = (uint32_t)r * 128;
        aM[mi] = (uint32_t)(r & 7) * 16;
    }
    #pragma unroll
    for (int nb = 0; nb < 2; nb++) {
        int r = nw * 32 + nb * 16 + ((lane & 7) + ((lane >> 4) << 3));
        bBase[nb] = (uint32_t)r * 128;
        bM[nb] = (uint32_t)(r & 7) * 16;
    }
    const uint32_t aU = (uint32_t)(lane >> 4) * 16;        // 0 or 16
    const uint32_t bU = (uint32_t)((lane >> 3) & 1) * 16;  // 0 or 16

    float acc1[2][4][4], acc2[2][4][4];
    float v1[4], v2[4];
    int   i1[4], i2[4];
    #pragma unroll
    for (int i = 0; i < 4; i++) { v1[i] = 3.4e38f; v2[i] = 3.4e38f; i1[i] = 0; i2[i] = 0; }

    auto load_stage = [&](int stg, int nt, int dc) {
        uint32_t sbase = sb + SM_TILES + (uint32_t)stg * STAGE_B;
        #pragma unroll
        for (int q = 0; q < 2; q++) {
            int s = tid + THREADS * q;
            int r = s >> 3, u = s & 7;
            uint32_t so = sw128((uint32_t)r * 128 + (uint32_t)u * 16);
            size_t ga = (size_t)(row0 + r) * DIMD + dc * KB + u * 8;
            size_t gb = (size_t)(nt * NT + r) * DIMD + dc * KB + u * 8;
            cp16(sbase + so,              g_Ahi + ga);
            cp16(sbase + ARR_B + so,      g_Alo + ga);
            cp16(sbase + 2 * ARR_B + so,  g_Bhi + gb);
            cp16(sbase + 3 * ARR_B + so,  g_Blo + gb);
        }
        asm volatile("cp.async.commit_group;" ::: "memory");
    };

    load_stage(0, 0, 0);

    for (int it = 0; it < NTILES * DCH; it++) {
        const int nt = it >> 3, dc = it & 7, stg = it & 1;
        if (it + 1 < NTILES * DCH) {
            load_stage(stg ^ 1, (it + 1) >> 3, (it + 1) & 7);
            asm volatile("cp.async.wait_group 1;" ::: "memory");
        } else {
            asm volatile("cp.async.wait_group 0;" ::: "memory");
        }
        __syncthreads();

        if (dc == 0) {
            if (tid < NT) csq_s[tid] = g_csq[nt * NT + tid];
            #pragma unroll
            for (int mi = 0; mi < 2; mi++)
                #pragma unroll
                for (int ni = 0; ni < 4; ni++)
                    #pragma unroll
                    for (int e = 0; e < 4; e++) { acc1[mi][ni][e] = 0.f; acc2[mi][ni][e] = 0.f; }
        }

        // ---- compute chunk ----
        const uint32_t sbase = sb + SM_TILES + (uint32_t)stg * STAGE_B;
        #pragma unroll
        for (int k16 = 0; k16 < 4; k16++) {
            const uint32_t ka = (uint32_t)k16 * 32 + aU;
            const uint32_t kb = (uint32_t)k16 * 32 + bU;
            uint32_t ahi[2][4], alo[2][4], bhi[2][4], blo[2][4];
            #pragma unroll
            for (int mi = 0; mi < 2; mi++)
                LDM_X4(ahi[mi][0], ahi[mi][1], ahi[mi][2], ahi[mi][3],
                       sbase + aBase[mi] + (ka ^ aM[mi]));
            #pragma unroll
            for (int nb = 0; nb < 2; nb++)
                LDM_X4(bhi[nb][0], bhi[nb][1], bhi[nb][2], bhi[nb][3],
                       sbase + 2 * ARR_B + bBase[nb] + (kb ^ bM[nb]));
            #pragma unroll
            for (int mi = 0; mi < 2; mi++)
                #pragma unroll
                for (int ni = 0; ni < 4; ni++)
                    MMA16816(acc1[mi][ni], ahi[mi],
                             bhi[ni >> 1][(ni & 1) * 2], bhi[ni >> 1][(ni & 1) * 2 + 1]);
            #pragma unroll
            for (int mi = 0; mi < 2; mi++)
                LDM_X4(alo[mi][0], alo[mi][1], alo[mi][2], alo[mi][3],
                       sbase + ARR_B + aBase[mi] + (ka ^ aM[mi]));
            #pragma unroll
            for (int mi = 0; mi < 2; mi++)
                #pragma unroll
                for (int ni = 0; ni < 4; ni++)
                    MMA16816(acc2[mi][ni], alo[mi],
                             bhi[ni >> 1][(ni & 1) * 2], bhi[ni >> 1][(ni & 1) * 2 + 1]);
            #pragma unroll
            for (int nb = 0; nb < 2; nb++)
                LDM_X4(blo[nb][0], blo[nb][1], blo[nb][2], blo[nb][3],
                       sbase + 3 * ARR_B + bBase[nb] + (kb ^ bM[nb]));
            #pragma unroll
            for (int mi = 0; mi < 2; mi++)
                #pragma unroll
                for (int ni = 0; ni < 4; ni++)
                    MMA16816(acc2[mi][ni], ahi[mi],
                             blo[ni >> 1][(ni & 1) * 2], blo[ni >> 1][(ni & 1) * 2 + 1]);
        }

        if (dc == DCH - 1) {
            // fold this column tile into per-thread top-2 (registers only)
            #pragma unroll
            for (int mi = 0; mi < 2; mi++)
                #pragma unroll
                for (int half = 0; half < 2; half++) {
                    const int rs = mi * 2 + half;
                    #pragma unroll
                    for (int ni = 0; ni < 4; ni++)
                        #pragma unroll
                        for (int e = 0; e < 2; e++) {
                            const int cl = nw * 32 + ni * 8 + (lane & 3) * 2 + e;
                            const int col = nt * NT + cl;
                            float dot = acc1[mi][ni][half * 2 + e]
                                      + acc2[mi][ni][half * 2 + e] * INV_LOSCALE;
                            float dist = csq_s[cl] - 2.0f * dot;
                            if (dist < v1[rs]) {
                                v2[rs] = v1[rs]; i2[rs] = i1[rs];
                                v1[rs] = dist;   i1[rs] = col;
                            } else if (dist < v2[rs]) {
                                v2[rs] = dist; i2[rs] = col;
                            }
                        }
                }
        }
        __syncthreads();
    }

    // ---- quad reduce of top-2 sets (lanes sharing a row differ in lane&3) ----
    #pragma unroll
    for (int rs = 0; rs < 4; rs++) {
        #pragma unroll
        for (int d = 1; d <= 2; d <<= 1) {
            float ov1 = __shfl_xor_sync(0xFFFFFFFFu, v1[rs], d);
            int   oi1 = __shfl_xor_sync(0xFFFFFFFFu, i1[rs], d);
            float ov2 = __shfl_xor_sync(0xFFFFFFFFu, v2[rs], d);
            int   oi2 = __shfl_xor_sync(0xFFFFFFFFu, i2[rs], d);
            bool oWins = (ov1 < v1[rs]) || (ov1 == v1[rs] && oi1 < i1[rs]);
            float w1 = oWins ? ov1 : v1[rs]; int wi1 = oWins ? oi1 : i1[rs];
            float l1 = oWins ? v1[rs] : ov1; int li1 = oWins ? i1[rs] : oi1;
            bool o2 = (ov2 < v2[rs]) || (ov2 == v2[rs] && oi2 < i2[rs]);
            float m2 = o2 ? ov2 : v2[rs];    int mi2 = o2 ? oi2 : i2[rs];
            bool lW = (l1 < m2) || (l1 == m2 && li1 < mi2);
            v1[rs] = w1; i1[rs] = wi1;
            v2[rs] = lW ? l1 : m2; i2[rs] = lW ? li1 : mi2;
        }
    }

    // ---- cross-warp (nw) merge via smem ----
    float4* cand = reinterpret_cast<float4*>(smem + SM_TILES);   // [row][nw] = (v1,i1,v2,i2)
    __syncthreads();
    if ((lane & 3) == 0) {
        #pragma unroll
        for (int rs = 0; rs < 4; rs++) {
            int row = mw * 32 + rs * 8 + (lane >> 2);
            cand[row * 4 + nw] = make_float4(v1[rs], __int_as_float(i1[rs]),
                                             v2[rs], __int_as_float(i2[rs]));
        }
    }
    __syncthreads();
    if (tid < MT) {
        float bv1 = 3.4e38f, bv2 = 3.4e38f;
        int   bi1 = 0,       bi2 = 0;
        #pragma unroll
        for (int t = 0; t < 4; t++) {
            float4 c = cand[tid * 4 + t];
            float cv1 = c.x, cv2 = c.z;
            int   ci1 = __float_as_int(c.y), ci2 = __float_as_int(c.w);
            bool oWins = (cv1 < bv1) || (cv1 == bv1 && ci1 < bi1);
            float w1 = oWins ? cv1 : bv1; int wi1 = oWins ? ci1 : bi1;
            float l1 = oWins ? bv1 : cv1; int li1 = oWins ? bi1 : ci1;
            bool o2 = (cv2 < bv2) || (cv2 == bv2 && ci2 < bi2);
            float m2 = o2 ? cv2 : bv2;    int mi2 = o2 ? ci2 : bi2;
            bool lW = (l1 < m2) || (l1 == m2 && li1 < mi2);
            bv1 = w1; bi1 = wi1;
            bv2 = lW ? l1 : m2; bi2 = lW ? li1 : mi2;
        }
        g_cand[row0 + tid] = make_int2(bi1, bi2);
    }
}

// ------------- phase 2: exact fp32 rescue (replicates R1 arithmetic) -------------
__global__ __launch_bounds__(256) void rescue_kernel(const float* __restrict__ A,
                                                     float* __restrict__ out) {
    int t = blockIdx.x * blockDim.x + threadIdx.x;   // one per (row, cand)
    int row = t >> 1;
    int2 cd = g_cand[row];
    int c = (t & 1) ? cd.y : cd.x;
    const float* a = A + (size_t)row * DIMD;
    const float* b = g_Bt + (size_t)c * DIMD;
    float acc = 0.f;
    #pragma unroll 8
    for (int d = 0; d < DIMD; d++) acc = fmaf(a[d], b[d], acc);   // strict d-order chain
    float dist = g_csq[c] - 2.0f * acc;

    float odist = __shfl_xor_sync(0xFFFFFFFFu, dist, 1);
    int   oc    = __shfl_xor_sync(0xFFFFFFFFu, c, 1);
    if ((t & 1) == 0) {
        int pick = (odist < dist || (odist == dist && oc < c)) ? oc : c;
        out[row] = (float)pick;
    }
}

// ------------- launch -------------
extern "C" void kernel_launch(void* const* d_in, const int* in_sizes, int n_in,
                              void* d_out, int out_size) {
    const float* features  = (const float*)d_in[0];   // [131072, 512]
    const float* centroids = (const float*)d_in[1];   // [512, 1024]
    float* out = (float*)d_out;

    cudaFuncSetAttribute(assign_mma, cudaFuncAttributeMaxDynamicSharedMemorySize, SMEM_TOTAL);

    split_feat<<<(int)(((size_t)NROWS * DIMD / 8 + 255) / 256), 256>>>(features);
    split_cent<<<(KCOLS * DIMD + 255) / 256, 256>>>(centroids);
    csq_kernel<<<(KCOLS + 255) / 256, 256>>>(centroids);
    assign_mma<<<NROWS / MT, THREADS, SMEM_TOTAL>>>();
    rescue_kernel<<<(2 * NROWS) / 256, 256>>>(features, out);
}

// round 5
// speedup vs baseline: 3.3114x; 1.2304x over previous
#include <cuda_runtime.h>
#include <cuda_fp16.h>
#include <cstdint>

#define NROWS  131072
#define DIMD   512
#define KCOLS  1024
#define MT     128        // rows per CTA
#define NT     128        // cols per tile
#define KB     64         // d per chunk
#define NTILES (KCOLS/NT) // 8
#define DCH    (DIMD/KB)  // 8
#define NIT    (NTILES*DCH)
#define THREADS 512
#define NSTAGE 4
#define LOSCALE 1024.0f
#define INV_LOSCALE 9.765625e-4f

// smem layout
#define SM_CSQ   0                   // 128 floats
#define SM_TILES 1024
#define ARR_B    (128*128)           // 16384 bytes per [128][64] half array
#define STAGE_B  (3*ARR_B)           // Ahi, Alo, Bhi = 48KB
#define SMEM_TOTAL (SM_TILES + NSTAGE*STAGE_B)   // 197632

// ------------- device globals (no allocations allowed) -------------
__device__ __align__(128) __half g_Ahi[(size_t)NROWS*DIMD];
__device__ __align__(128) __half g_Alo[(size_t)NROWS*DIMD];
__device__ __align__(128) __half g_Bhi[(size_t)KCOLS*DIMD];   // transposed [k][d]
__device__ __align__(128) float  g_Bt[(size_t)KCOLS*DIMD];    // fp32 transposed [k][d]
__device__ float g_csq[KCOLS];
__device__ int4  g_cand[NROWS];

// ------------- helpers -------------
__device__ __forceinline__ uint32_t smem_u32(const void* p) {
    uint32_t a;
    asm("{ .reg .u64 t; cvta.to.shared.u64 t, %1; cvt.u32.u64 %0, t; }" : "=r"(a) : "l"(p));
    return a;
}
__device__ __forceinline__ uint32_t sw128(uint32_t o) { return o ^ ((o >> 3) & 0x70); }

__device__ __forceinline__ void cp16(uint32_t s, const void* g) {
    size_t ga = __cvta_generic_to_global(g);
    asm volatile("cp.async.cg.shared.global [%0], [%1], 16;" :: "r"(s), "l"(ga) : "memory");
}

#define LDM_X4(r0,r1,r2,r3,addr) \
    asm volatile("ldmatrix.sync.aligned.m8n8.x4.shared.b16 {%0,%1,%2,%3}, [%4];" \
        : "=r"(r0),"=r"(r1),"=r"(r2),"=r"(r3) : "r"(addr))

#define MMA16816(d, a, b0, b1) \
    asm volatile("mma.sync.aligned.m16n8k16.row.col.f32.f16.f16.f32 " \
        "{%0,%1,%2,%3},{%4,%5,%6,%7},{%8,%9},{%0,%1,%2,%3};" \
        : "+f"((d)[0]),"+f"((d)[1]),"+f"((d)[2]),"+f"((d)[3]) \
        : "r"((a)[0]),"r"((a)[1]),"r"((a)[2]),"r"((a)[3]),"r"(b0),"r"(b1))

// ------------- precompute kernels -------------
__global__ void split_feat(const float* __restrict__ A) {
    size_t i = (size_t)blockIdx.x * blockDim.x + threadIdx.x;   // 8 elems each
    if (i >= (size_t)NROWS * DIMD / 8) return;
    const float4* a4 = reinterpret_cast<const float4*>(A) + i * 2;
    float4 v0 = a4[0], v1 = a4[1];
    float x[8] = {v0.x, v0.y, v0.z, v0.w, v1.x, v1.y, v1.z, v1.w};
    __half h[8], l[8];
    #pragma unroll
    for (int j = 0; j < 8; j++) {
        h[j] = __float2half_rn(x[j]);
        l[j] = __float2half_rn((x[j] - __half2float(h[j])) * LOSCALE);
    }
    reinterpret_cast<uint4*>(g_Ahi)[i] = *reinterpret_cast<uint4*>(h);
    reinterpret_cast<uint4*>(g_Alo)[i] = *reinterpret_cast<uint4*>(l);
}

__global__ void split_cent(const float* __restrict__ B) {
    int i = blockIdx.x * blockDim.x + threadIdx.x;   // over [k][d]
    if (i >= KCOLS * DIMD) return;
    int k = i / DIMD, d = i % DIMD;
    float x = B[(size_t)d * KCOLS + k];
    g_Bhi[i] = __float2half_rn(x);
    g_Bt[i]  = x;
}

__global__ void csq_kernel(const float* __restrict__ c) {
    int k = blockIdx.x * blockDim.x + threadIdx.x;
    if (k < KCOLS) {
        float s = 0.f;
        #pragma unroll 8
        for (int d = 0; d < DIMD; d++) {
            float v = c[(size_t)d * KCOLS + k];
            s += v * v;
        }
        g_csq[k] = s;
    }
}

// ------------- phase 1: 2-pass screening GEMM + top-2/top-3 -------------
__global__ __launch_bounds__(THREADS, 1) void assign_mma() {
    extern __shared__ char smem[];
    const uint32_t sb = smem_u32(smem);
    const int tid = threadIdx.x;
    const int lane = tid & 31;
    const int w = tid >> 5;
    const int mw = w >> 2;          // 0..3 (M)
    const int nw = w & 3;           // 0..3 (N)
    const int row0 = blockIdx.x * MT;
    float* csq_s = reinterpret_cast<float*>(smem + SM_CSQ);

    // ldmatrix address precomputes
    uint32_t aBase[2], aM[2], bBase[2], bM[2];
    #pragma unroll
    for (int mi = 0; mi < 2; mi++) {
        int r = mw * 32 + mi * 16 + (lane & 15);
        aBase[mi] = (uint32_t)r * 128;
        aM[mi] = (uint32_t)(r & 7) * 16;
    }
    #pragma unroll
    for (int nb = 0; nb < 2; nb++) {
        int r = nw * 32 + nb * 16 + ((lane & 7) + ((lane >> 4) << 3));
        bBase[nb] = (uint32_t)r * 128;
        bM[nb] = (uint32_t)(r & 7) * 16;
    }
    const uint32_t aU = (uint32_t)(lane >> 4) * 16;        // 0 or 16
    const uint32_t bU = (uint32_t)((lane >> 3) & 1) * 16;  // 0 or 16

    float acc1[2][4][4], acc2[2][4][4];
    float v1[4], v2[4];
    int   i1[4], i2[4];
    #pragma unroll
    for (int i = 0; i < 4; i++) { v1[i] = 3.4e38f; v2[i] = 3.4e38f; i1[i] = 0; i2[i] = 0; }

    auto load_stage = [&](int stg, int nt, int dc) {
        uint32_t sbase = sb + SM_TILES + (uint32_t)stg * STAGE_B;
        #pragma unroll
        for (int q = 0; q < 2; q++) {
            int s = tid + THREADS * q;
            int r = s >> 3, u = s & 7;
            uint32_t so = sw128((uint32_t)r * 128 + (uint32_t)u * 16);
            size_t ga = (size_t)(row0 + r) * DIMD + dc * KB + u * 8;
            size_t gb = (size_t)(nt * NT + r) * DIMD + dc * KB + u * 8;
            cp16(sbase + so,              g_Ahi + ga);
            cp16(sbase + ARR_B + so,      g_Alo + ga);
            cp16(sbase + 2 * ARR_B + so,  g_Bhi + gb);
        }
        asm volatile("cp.async.commit_group;" ::: "memory");
    };

    // prologue: fill 3 stages
    load_stage(0, 0, 0);
    load_stage(1, 0, 1);
    load_stage(2, 0, 2);

    for (int it = 0; it < NIT; it++) {
        const int nt = it >> 3, dc = it & 7, stg = it & (NSTAGE - 1);
        asm volatile("cp.async.wait_group %0;" :: "n"(NSTAGE - 2) : "memory");
        __syncthreads();   // stage `it` arrived AND all warps finished stage it-1's compute
        if (it + 3 < NIT)
            load_stage((it + 3) & (NSTAGE - 1), (it + 3) >> 3, (it + 3) & 7);

        if (dc == 0) {
            if (tid < NT) csq_s[tid] = g_csq[nt * NT + tid];
            #pragma unroll
            for (int mi = 0; mi < 2; mi++)
                #pragma unroll
                for (int ni = 0; ni < 4; ni++)
                    #pragma unroll
                    for (int e = 0; e < 4; e++) { acc1[mi][ni][e] = 0.f; acc2[mi][ni][e] = 0.f; }
        }

        // ---- compute chunk ----
        const uint32_t sbase = sb + SM_TILES + (uint32_t)stg * STAGE_B;
        #pragma unroll
        for (int k16 = 0; k16 < 4; k16++) {
            const uint32_t ka = (uint32_t)k16 * 32 + aU;
            const uint32_t kb = (uint32_t)k16 * 32 + bU;
            uint32_t ahi[2][4], alo[2][4], bhi[2][4];
            #pragma unroll
            for (int mi = 0; mi < 2; mi++)
                LDM_X4(ahi[mi][0], ahi[mi][1], ahi[mi][2], ahi[mi][3],
                       sbase + aBase[mi] + (ka ^ aM[mi]));
            #pragma unroll
            for (int nb = 0; nb < 2; nb++)
                LDM_X4(bhi[nb][0], bhi[nb][1], bhi[nb][2], bhi[nb][3],
                       sbase + 2 * ARR_B + bBase[nb] + (kb ^ bM[nb]));
            #pragma unroll
            for (int mi = 0; mi < 2; mi++)
                #pragma unroll
                for (int ni = 0; ni < 4; ni++)
                    MMA16816(acc1[mi][ni], ahi[mi],
                             bhi[ni >> 1][(ni & 1) * 2], bhi[ni >> 1][(ni & 1) * 2 + 1]);
            #pragma unroll
            for (int mi = 0; mi < 2; mi++)
                LDM_X4(alo[mi][0], alo[mi][1], alo[mi][2], alo[mi][3],
                       sbase + ARR_B + aBase[mi] + (ka ^ aM[mi]));
            #pragma unroll
            for (int mi = 0; mi < 2; mi++)
                #pragma unroll
                for (int ni = 0; ni < 4; ni++)
                    MMA16816(acc2[mi][ni], alo[mi],
                             bhi[ni >> 1][(ni & 1) * 2], bhi[ni >> 1][(ni & 1) * 2 + 1]);
        }

        if (dc == DCH - 1) {
            // fold this column tile into per-thread top-2 (registers only)
            #pragma unroll
            for (int mi = 0; mi < 2; mi++)
                #pragma unroll
                for (int half = 0; half < 2; half++) {
                    const int rs = mi * 2 + half;
                    #pragma unroll
                    for (int ni = 0; ni < 4; ni++)
                        #pragma unroll
                        for (int e = 0; e < 2; e++) {
                            const int cl = nw * 32 + ni * 8 + (lane & 3) * 2 + e;
                            const int col = nt * NT + cl;
                            float dot = acc1[mi][ni][half * 2 + e]
                                      + acc2[mi][ni][half * 2 + e] * INV_LOSCALE;
                            float dist = csq_s[cl] - 2.0f * dot;
                            if (dist < v1[rs]) {
                                v2[rs] = v1[rs]; i2[rs] = i1[rs];
                                v1[rs] = dist;   i1[rs] = col;
                            } else if (dist < v2[rs]) {
                                v2[rs] = dist; i2[rs] = col;
                            }
                        }
                }
        }
    }
    __syncthreads();

    // ---- quad reduce of top-2 sets (lanes sharing a row differ in lane&3) ----
    #pragma unroll
    for (int rs = 0; rs < 4; rs++) {
        #pragma unroll
        for (int d = 1; d <= 2; d <<= 1) {
            float ov1 = __shfl_xor_sync(0xFFFFFFFFu, v1[rs], d);
            int   oi1 = __shfl_xor_sync(0xFFFFFFFFu, i1[rs], d);
            float ov2 = __shfl_xor_sync(0xFFFFFFFFu, v2[rs], d);
            int   oi2 = __shfl_xor_sync(0xFFFFFFFFu, i2[rs], d);
            bool oWins = (ov1 < v1[rs]) || (ov1 == v1[rs] && oi1 < i1[rs]);
            float w1 = oWins ? ov1 : v1[rs]; int wi1 = oWins ? oi1 : i1[rs];
            float l1 = oWins ? v1[rs] : ov1; int li1 = oWins ? i1[rs] : oi1;
            bool o2 = (ov2 < v2[rs]) || (ov2 == v2[rs] && oi2 < i2[rs]);
            float m2 = o2 ? ov2 : v2[rs];    int mi2 = o2 ? oi2 : i2[rs];
            bool lW = (l1 < m2) || (l1 == m2 && li1 < mi2);
            v1[rs] = w1; i1[rs] = wi1;
            v2[rs] = lW ? l1 : m2; i2[rs] = lW ? li1 : mi2;
        }
    }

    // ---- cross-warp (nw) merge via smem -> global top-3 ----
    float4* cand = reinterpret_cast<float4*>(smem + SM_TILES);   // [row][nw] = (v1,i1,v2,i2)
    if ((lane & 3) == 0) {
        #pragma unroll
        for (int rs = 0; rs < 4; rs++) {
            int row = mw * 32 + rs * 8 + (lane >> 2);
            cand[row * 4 + nw] = make_float4(v1[rs], __int_as_float(i1[rs]),
                                             v2[rs], __int_as_float(i2[rs]));
        }
    }
    __syncthreads();
    if (tid < MT) {
        float t1 = 3.4e38f, t2 = 3.4e38f, t3 = 3.4e38f;
        int   j1 = 0, j2 = 0, j3 = 0;
        #pragma unroll
        for (int t = 0; t < 4; t++) {
            float4 c = cand[tid * 4 + t];
            #pragma unroll
            for (int h = 0; h < 2; h++) {
                float v = h ? c.z : c.x;
                int   i = __float_as_int(h ? c.w : c.y);
                if (v < t1 || (v == t1 && i < j1)) {
                    t3 = t2; j3 = j2; t2 = t1; j2 = j1; t1 = v; j1 = i;
                } else if (v < t2 || (v == t2 && i < j2)) {
                    t3 = t2; j3 = j2; t2 = v; j2 = i;
                } else if (v < t3 || (v == t3 && i < j3)) {
                    t3 = v; j3 = i;
                }
            }
        }
        g_cand[row0 + tid] = make_int4(j1, j2, j3, j3);
    }
}

// ------------- phase 2: exact fp32 rescue (sequential-d chain, as R1) -------------
__global__ __launch_bounds__(256) void rescue_kernel(const float* __restrict__ A,
                                                     float* __restrict__ out) {
    int t = blockIdx.x * blockDim.x + threadIdx.x;   // 4 threads per row
    int row = t >> 2;
    int4 cd = g_cand[row];
    int c = (t & 3) == 0 ? cd.x : ((t & 3) == 1 ? cd.y : ((t & 3) == 2 ? cd.z : cd.w));
    const float* a = A + (size_t)row * DIMD;
    const float* b = g_Bt + (size_t)c * DIMD;
    float acc = 0.f;
    #pragma unroll 8
    for (int d = 0; d < DIMD; d++) acc = fmaf(a[d], b[d], acc);   // strict d-order chain
    float dist = g_csq[c] - 2.0f * acc;

    #pragma unroll
    for (int s = 1; s <= 2; s <<= 1) {
        float od = __shfl_xor_sync(0xFFFFFFFFu, dist, s);
        int   oc = __shfl_xor_sync(0xFFFFFFFFu, c, s);
        if (od < dist || (od == dist && oc < c)) { dist = od; c = oc; }
    }
    if ((t & 3) == 0) out[row] = (float)c;
}

// ------------- launch -------------
extern "C" void kernel_launch(void* const* d_in, const int* in_sizes, int n_in,
                              void* d_out, int out_size) {
    const float* features  = (const float*)d_in[0];   // [131072, 512]
    const float* centroids = (const float*)d_in[1];   // [512, 1024]
    float* out = (float*)d_out;

    cudaFuncSetAttribute(assign_mma, cudaFuncAttributeMaxDynamicSharedMemorySize, SMEM_TOTAL);

    split_feat<<<(int)(((size_t)NROWS * DIMD / 8 + 255) / 256), 256>>>(features);
    split_cent<<<(KCOLS * DIMD + 255) / 256, 256>>>(centroids);
    csq_kernel<<<(KCOLS + 255) / 256, 256>>>(centroids);
    assign_mma<<<NROWS / MT, THREADS, SMEM_TOTAL>>>();
    rescue_kernel<<<(4 * NROWS) / 256, 256>>>(features, out);
}

// round 6
// speedup vs baseline: 3.9788x; 1.2015x over previous
#include <cuda_runtime.h>
#include <cuda_fp16.h>
#include <cstdint>

#define NROWS  131072
#define DIMD   512
#define KCOLS  1024
#define MT     128        // rows per CTA
#define NT     128        // cols per tile
#define KB     64         // d per chunk
#define NTILES (KCOLS/NT) // 8
#define DCH    (DIMD/KB)  // 8
#define NIT    (NTILES*DCH)
#define THREADS 512
#define NSTAGE 6

// smem layout
#define SM_CSQ   0                   // 128 floats
#define SM_TILES 1024
#define ARR_B    (128*128)           // 16384 bytes per [128][64] half array
#define STAGE_B  (2*ARR_B)           // Ahi, Bhi = 32KB
#define SMEM_TOTAL (SM_TILES + NSTAGE*STAGE_B)   // 197632

// ------------- device globals (no allocations allowed) -------------
__device__ __align__(128) __half g_Ahi[(size_t)NROWS*DIMD];
__device__ __align__(128) __half g_Bhi[(size_t)KCOLS*DIMD];   // transposed [k][d]
__device__ __align__(128) float  g_Bt[(size_t)KCOLS*DIMD];    // fp32 transposed [k][d]
__device__ float g_csq[KCOLS];
__device__ int4  g_cand[NROWS];

// ------------- helpers -------------
__device__ __forceinline__ uint32_t smem_u32(const void* p) {
    uint32_t a;
    asm("{ .reg .u64 t; cvta.to.shared.u64 t, %1; cvt.u32.u64 %0, t; }" : "=r"(a) : "l"(p));
    return a;
}
__device__ __forceinline__ uint32_t sw128(uint32_t o) { return o ^ ((o >> 3) & 0x70); }

__device__ __forceinline__ void cp16(uint32_t s, const void* g) {
    size_t ga = __cvta_generic_to_global(g);
    asm volatile("cp.async.cg.shared.global [%0], [%1], 16;" :: "r"(s), "l"(ga) : "memory");
}

#define LDM_X4(r0,r1,r2,r3,addr) \
    asm volatile("ldmatrix.sync.aligned.m8n8.x4.shared.b16 {%0,%1,%2,%3}, [%4];" \
        : "=r"(r0),"=r"(r1),"=r"(r2),"=r"(r3) : "r"(addr))

#define MMA16816(d, a, b0, b1) \
    asm volatile("mma.sync.aligned.m16n8k16.row.col.f32.f16.f16.f32 " \
        "{%0,%1,%2,%3},{%4,%5,%6,%7},{%8,%9},{%0,%1,%2,%3};" \
        : "+f"((d)[0]),"+f"((d)[1]),"+f"((d)[2]),"+f"((d)[3]) \
        : "r"((a)[0]),"r"((a)[1]),"r"((a)[2]),"r"((a)[3]),"r"(b0),"r"(b1))

// ------------- precompute kernels -------------
__global__ void split_feat(const float* __restrict__ A) {
    size_t i = (size_t)blockIdx.x * blockDim.x + threadIdx.x;   // 8 elems each
    if (i >= (size_t)NROWS * DIMD / 8) return;
    const float4* a4 = reinterpret_cast<const float4*>(A) + i * 2;
    float4 v0 = a4[0], v1 = a4[1];
    float x[8] = {v0.x, v0.y, v0.z, v0.w, v1.x, v1.y, v1.z, v1.w};
    __half h[8];
    #pragma unroll
    for (int j = 0; j < 8; j++) h[j] = __float2half_rn(x[j]);
    reinterpret_cast<uint4*>(g_Ahi)[i] = *reinterpret_cast<uint4*>(h);
}

__global__ void split_cent(const float* __restrict__ B) {
    int i = blockIdx.x * blockDim.x + threadIdx.x;   // over [k][d]
    if (i >= KCOLS * DIMD) return;
    int k = i / DIMD, d = i % DIMD;
    float x = B[(size_t)d * KCOLS + k];
    g_Bhi[i] = __float2half_rn(x);
    g_Bt[i]  = x;
}

__global__ void csq_kernel(const float* __restrict__ c) {
    int k = blockIdx.x * blockDim.x + threadIdx.x;
    if (k < KCOLS) {
        float s = 0.f;
        #pragma unroll 8
        for (int d = 0; d < DIMD; d++) {
            float v = c[(size_t)d * KCOLS + k];
            s += v * v;
        }
        g_csq[k] = s;
    }
}

// ------------- phase 1: 1-pass fp16 screening GEMM + top-2/thread -> top-4/row -------------
__global__ __launch_bounds__(THREADS, 1) void assign_mma() {
    extern __shared__ char smem[];
    const uint32_t sb = smem_u32(smem);
    const int tid = threadIdx.x;
    const int lane = tid & 31;
    const int w = tid >> 5;
    const int mw = w >> 2;          // 0..3 (M)
    const int nw = w & 3;           // 0..3 (N)
    const int row0 = blockIdx.x * MT;
    float* csq_s = reinterpret_cast<float*>(smem + SM_CSQ);

    // ldmatrix address precomputes
    uint32_t aBase[2], aM[2], bBase[2], bM[2];
    #pragma unroll
    for (int mi = 0; mi < 2; mi++) {
        int r = mw * 32 + mi * 16 + (lane & 15);
        aBase[mi] = (uint32_t)r * 128;
        aM[mi] = (uint32_t)(r & 7) * 16;
    }
    #pragma unroll
    for (int nb = 0; nb < 2; nb++) {
        int r = nw * 32 + nb * 16 + ((lane & 7) + ((lane >> 4) << 3));
        bBase[nb] = (uint32_t)r * 128;
        bM[nb] = (uint32_t)(r & 7) * 16;
    }
    const uint32_t aU = (uint32_t)(lane >> 4) * 16;        // 0 or 16
    const uint32_t bU = (uint32_t)((lane >> 3) & 1) * 16;  // 0 or 16

    float acc1[2][4][4];
    float v1[4], v2[4];
    int   i1[4], i2[4];
    #pragma unroll
    for (int i = 0; i < 4; i++) { v1[i] = 3.4e38f; v2[i] = 3.4e38f; i1[i] = 0; i2[i] = 0; }

    auto load_stage = [&](int stg, int nt, int dc) {
        uint32_t sbase = sb + SM_TILES + (uint32_t)stg * STAGE_B;
        #pragma unroll
        for (int q = 0; q < 2; q++) {
            int s = tid + THREADS * q;
            int r = s >> 3, u = s & 7;
            uint32_t so = sw128((uint32_t)r * 128 + (uint32_t)u * 16);
            size_t ga = (size_t)(row0 + r) * DIMD + dc * KB + u * 8;
            size_t gb = (size_t)(nt * NT + r) * DIMD + dc * KB + u * 8;
            cp16(sbase + so,          g_Ahi + ga);
            cp16(sbase + ARR_B + so,  g_Bhi + gb);
        }
        asm volatile("cp.async.commit_group;" ::: "memory");
    };

    // prologue: fill NSTAGE-1 stages
    #pragma unroll
    for (int p = 0; p < NSTAGE - 1; p++) load_stage(p, p >> 3, p & 7);

    for (int it = 0; it < NIT; it++) {
        const int nt = it >> 3, dc = it & 7, stg = it % NSTAGE;
        asm volatile("cp.async.wait_group %0;" :: "n"(NSTAGE - 2) : "memory");
        __syncthreads();   // stage `it` arrived AND all warps done with slot being reloaded
        if (it + NSTAGE - 1 < NIT)
            load_stage((it + NSTAGE - 1) % NSTAGE, (it + NSTAGE - 1) >> 3, (it + NSTAGE - 1) & 7);

        if (dc == 0) {
            if (tid < NT) csq_s[tid] = g_csq[nt * NT + tid];
            #pragma unroll
            for (int mi = 0; mi < 2; mi++)
                #pragma unroll
                for (int ni = 0; ni < 4; ni++)
                    #pragma unroll
                    for (int e = 0; e < 4; e++) acc1[mi][ni][e] = 0.f;
        }

        // ---- compute chunk ----
        const uint32_t sbase = sb + SM_TILES + (uint32_t)stg * STAGE_B;
        #pragma unroll
        for (int k16 = 0; k16 < 4; k16++) {
            const uint32_t ka = (uint32_t)k16 * 32 + aU;
            const uint32_t kb = (uint32_t)k16 * 32 + bU;
            uint32_t ahi[2][4], bhi[2][4];
            #pragma unroll
            for (int mi = 0; mi < 2; mi++)
                LDM_X4(ahi[mi][0], ahi[mi][1], ahi[mi][2], ahi[mi][3],
                       sbase + aBase[mi] + (ka ^ aM[mi]));
            #pragma unroll
            for (int nb = 0; nb < 2; nb++)
                LDM_X4(bhi[nb][0], bhi[nb][1], bhi[nb][2], bhi[nb][3],
                       sbase + ARR_B + bBase[nb] + (kb ^ bM[nb]));
            #pragma unroll
            for (int mi = 0; mi < 2; mi++)
                #pragma unroll
                for (int ni = 0; ni < 4; ni++)
                    MMA16816(acc1[mi][ni], ahi[mi],
                             bhi[ni >> 1][(ni & 1) * 2], bhi[ni >> 1][(ni & 1) * 2 + 1]);
        }

        if (dc == DCH - 1) {
            // fold this column tile into per-thread top-2 (registers only)
            #pragma unroll
            for (int mi = 0; mi < 2; mi++)
                #pragma unroll
                for (int half = 0; half < 2; half++) {
                    const int rs = mi * 2 + half;
                    #pragma unroll
                    for (int ni = 0; ni < 4; ni++)
                        #pragma unroll
                        for (int e = 0; e < 2; e++) {
                            const int cl = nw * 32 + ni * 8 + (lane & 3) * 2 + e;
                            const int col = nt * NT + cl;
                            float dist = csq_s[cl] - 2.0f * acc1[mi][ni][half * 2 + e];
                            if (dist < v1[rs]) {
                                v2[rs] = v1[rs]; i2[rs] = i1[rs];
                                v1[rs] = dist;   i1[rs] = col;
                            } else if (dist < v2[rs]) {
                                v2[rs] = dist; i2[rs] = col;
                            }
                        }
                }
        }
    }
    __syncthreads();

    // ---- dump all per-thread top-2 to smem: 16 threads per row x (v1,i1,v2,i2) ----
    float4* cand = reinterpret_cast<float4*>(smem + SM_TILES);   // [row][slot] slot=nw*4+(lane&3)
    {
        const int slot = nw * 4 + (lane & 3);
        #pragma unroll
        for (int rs = 0; rs < 4; rs++) {
            int row = mw * 32 + rs * 8 + (lane >> 2);
            cand[row * 16 + slot] = make_float4(v1[rs], __int_as_float(i1[rs]),
                                                v2[rs], __int_as_float(i2[rs]));
        }
    }
    __syncthreads();

    // ---- one thread per row: top-4 of 32 candidates (lexicographic) ----
    if (tid < MT) {
        float t1 = 3.4e38f, t2 = 3.4e38f, t3 = 3.4e38f, t4 = 3.4e38f;
        int   j1 = 0, j2 = 0, j3 = 0, j4 = 0;
        #pragma unroll 4
        for (int t = 0; t < 16; t++) {
            float4 c = cand[tid * 16 + t];
            #pragma unroll
            for (int h = 0; h < 2; h++) {
                float v = h ? c.z : c.x;
                int   i = __float_as_int(h ? c.w : c.y);
                if (v < t1 || (v == t1 && i < j1)) {
                    t4 = t3; j4 = j3; t3 = t2; j3 = j2; t2 = t1; j2 = j1; t1 = v; j1 = i;
                } else if (v < t2 || (v == t2 && i < j2)) {
                    t4 = t3; j4 = j3; t3 = t2; j3 = j2; t2 = v; j2 = i;
                } else if (v < t3 || (v == t3 && i < j3)) {
                    t4 = t3; j4 = j3; t3 = v; j3 = i;
                } else if (v < t4 || (v == t4 && i < j4)) {
                    t4 = v; j4 = i;
                }
            }
        }
        g_cand[row0 + tid] = make_int4(j1, j2, j3, j4);
    }
}

// ------------- phase 2: exact fp32 rescue (sequential-d chain, as R1) -------------
__global__ __launch_bounds__(256) void rescue_kernel(const float* __restrict__ A,
                                                     float* __restrict__ out) {
    int t = blockIdx.x * blockDim.x + threadIdx.x;   // 4 threads per row
    int row = t >> 2;
    int4 cd = g_cand[row];
    int c = (t & 3) == 0 ? cd.x : ((t & 3) == 1 ? cd.y : ((t & 3) == 2 ? cd.z : cd.w));
    const float* a = A + (size_t)row * DIMD;
    const float* b = g_Bt + (size_t)c * DIMD;
    float acc = 0.f;
    #pragma unroll 8
    for (int d = 0; d < DIMD; d++) acc = fmaf(a[d], b[d], acc);   // strict d-order chain
    float dist = g_csq[c] - 2.0f * acc;

    #pragma unroll
    for (int s = 1; s <= 2; s <<= 1) {
        float od = __shfl_xor_sync(0xFFFFFFFFu, dist, s);
        int   oc = __shfl_xor_sync(0xFFFFFFFFu, c, s);
        if (od < dist || (od == dist && oc < c)) { dist = od; c = oc; }
    }
    if ((t & 3) == 0) out[row] = (float)c;
}

// ------------- launch -------------
extern "C" void kernel_launch(void* const* d_in, const int* in_sizes, int n_in,
                              void* d_out, int out_size) {
    const float* features  = (const float*)d_in[0];   // [131072, 512]
    const float* centroids = (const float*)d_in[1];   // [512, 1024]
    float* out = (float*)d_out;

    cudaFuncSetAttribute(assign_mma, cudaFuncAttributeMaxDynamicSharedMemorySize, SMEM_TOTAL);

    split_feat<<<(int)(((size_t)NROWS * DIMD / 8 + 255) / 256), 256>>>(features);
    split_cent<<<(KCOLS * DIMD + 255) / 256, 256>>>(centroids);
    csq_kernel<<<(KCOLS + 255) / 256, 256>>>(centroids);
    assign_mma<<<NROWS / MT, THREADS, SMEM_TOTAL>>>();
    rescue_kernel<<<(4 * NROWS) / 256, 256>>>(features, out);
}